// round 4
// baseline (speedup 1.0000x reference)
#include <cuda_runtime.h>

// ChunkedValueCrossAttn: softmax over a single context token == 1.0, so
// y[b,c,h,w] = (Wo @ (Wv @ context[b]))[c] + bo[c] — a constant per (b,c)
// broadcast over HxW. x/Wq/Wk are dead inputs.
//
// Shapes: B=2, C=64, H=W=1024, inner=32, ctx=16.
// out: [2, 64, 1024, 1024] f32 = 536.9 MB write-only -> HBM store-bound.
//
// Fully fused, barrier-free: every warp redundantly computes its block's
// constant (16 FMAs/lane + xor-butterfly reduce -> sum lands in ALL lanes;
// no shared memory, no __syncthreads), then streams 16 float4 stores per
// thread with evict-first (.cs) hints. Each block's 64KB range lies inside
// exactly one (b,c) slab (4096 f4 divides 2^18 f4).

#define B_       2
#define CQ_      64
#define INNER_   32
#define CTX_     16
#define TPB_     256
#define F4_PER_THREAD_ 16
#define F4_PER_BLOCK_  (TPB_ * F4_PER_THREAD_)   // 4096 float4 = 64KB

__global__ void __launch_bounds__(TPB_) fused_fill_kernel(
        float4* __restrict__ out,
        const float* __restrict__ context,
        const float* __restrict__ Wv,
        const float* __restrict__ Wo,
        const float* __restrict__ bo) {
    unsigned int slab = blockIdx.x >> 6;       // 64 blocks per slab
    unsigned int b = slab >> 6;                // batch index
    unsigned int c = slab & 63u;               // channel index

    // Every warp computes the constant redundantly — no cross-warp sync.
    int o = threadIdx.x & 31;                  // inner index, one per lane
    float v = 0.f;
    #pragma unroll
    for (int j = 0; j < CTX_; ++j)
        v += Wv[o * CTX_ + j] * context[b * CTX_ + j];
    float p = Wo[c * INNER_ + o] * v;
    #pragma unroll
    for (int off = 16; off > 0; off >>= 1)
        p += __shfl_xor_sync(0xFFFFFFFFu, p, off);   // all lanes hold the sum
    float val = p + bo[c];

    float4 f = make_float4(val, val, val, val);
    unsigned int base = blockIdx.x * (unsigned)F4_PER_BLOCK_ + threadIdx.x;
    #pragma unroll
    for (int k = 0; k < F4_PER_THREAD_; ++k)
        __stcs(out + base + k * (unsigned)TPB_, f);  // streaming (evict-first)
}

extern "C" void kernel_launch(void* const* d_in, const int* in_sizes, int n_in,
                              void* d_out, int out_size) {
    // metadata order: x, context, Wq, Wk, Wv, Wo, bo
    const float* context = (const float*)d_in[1];
    const float* Wv      = (const float*)d_in[4];
    const float* Wo      = (const float*)d_in[5];
    const float* bo      = (const float*)d_in[6];

    // out_size = 134,217,728 floats = 33,554,432 float4 -> 8192 blocks exact
    int n4 = out_size / 4;
    int blocks = n4 / F4_PER_BLOCK_;
    fused_fill_kernel<<<blocks, TPB_>>>((float4*)d_out, context, Wv, Wo, bo);
}